// round 1
// baseline (speedup 1.0000x reference)
#include <cuda_runtime.h>
#include <math.h>
#include <float.h>

// ---------------------------------------------------------------------------
// PointEncoder: FF1 -> FF2 -> 4x attention -> concat -> FF_final
// N=8192, IN_F=3, D=512, MD=128, OUT_F=1024. All fp32.
// ---------------------------------------------------------------------------

#define NROWS 8192
#define DMODEL 512
#define MDIM 128
#define OUTF 1024

// Static scratch (allocation-free rule: __device__ globals)
__device__ float g_h[NROWS * DMODEL];              // FF1 output
__device__ float g_tmp[NROWS * DMODEL];            // FF2 output (attention input 1)
__device__ float g_Q[NROWS * MDIM];
__device__ float g_Km[NROWS * MDIM];
__device__ float g_V[NROWS * DMODEL];
__device__ float g_S[(size_t)NROWS * NROWS];       // 256 MB attention scores
__device__ float g_AV[NROWS * DMODEL];
__device__ float g_cat[NROWS * 4 * DMODEL];        // concat of a1..a4

// ---------------------------------------------------------------------------
// Reductions
// ---------------------------------------------------------------------------
__device__ __forceinline__ float warpReduceSum(float v) {
#pragma unroll
    for (int o = 16; o > 0; o >>= 1) v += __shfl_xor_sync(0xffffffff, v, o);
    return v;
}
__device__ __forceinline__ float warpReduceMax(float v) {
#pragma unroll
    for (int o = 16; o > 0; o >>= 1) v = fmaxf(v, __shfl_xor_sync(0xffffffff, v, o));
    return v;
}

__device__ float blockReduceSum(float v) {
    __shared__ float sh[32];
    __shared__ float res;
    int lane = threadIdx.x & 31, wid = threadIdx.x >> 5;
    v = warpReduceSum(v);
    if (lane == 0) sh[wid] = v;
    __syncthreads();
    int nw = (blockDim.x + 31) >> 5;
    float t = (threadIdx.x < nw) ? sh[threadIdx.x] : 0.0f;
    if (wid == 0) {
        t = warpReduceSum(t);
        if (lane == 0) res = t;
    }
    __syncthreads();
    return res;
}

__device__ float blockReduceMax(float v) {
    __shared__ float sh[32];
    __shared__ float res;
    int lane = threadIdx.x & 31, wid = threadIdx.x >> 5;
    v = warpReduceMax(v);
    if (lane == 0) sh[wid] = v;
    __syncthreads();
    int nw = (blockDim.x + 31) >> 5;
    float t = (threadIdx.x < nw) ? sh[threadIdx.x] : -FLT_MAX;
    if (wid == 0) {
        t = warpReduceMax(t);
        if (lane == 0) res = t;
    }
    __syncthreads();
    return res;
}

// ---------------------------------------------------------------------------
// Tiled SGEMM: C[M,N] = alpha * A @ op(B) + bias
//   BT = false: B is [K,N] row-major (nn)
//   BT = true : B is [N,K] row-major (nt, i.e. C = A @ B^T)
// Requirements: M%128==0, N%128==0, K%8==0, lda/ldb/ldc %4==0.
// 128x128 block tile, 8-deep K, 256 threads, 8x8 per thread.
// ---------------------------------------------------------------------------
#define BM 128
#define BN 128
#define BK 8

template <bool BT>
__global__ void __launch_bounds__(256, 2) sgemm_kernel(
    int M, int N, int K,
    const float* __restrict__ A, int lda,
    const float* __restrict__ B, int ldb,
    float* __restrict__ C, int ldc,
    const float* __restrict__ bias, float alpha)
{
    __shared__ float As[BK][BM];
    __shared__ float Bs[BK][BN];

    const int t  = threadIdx.x;
    const int bx = blockIdx.x;   // N tiles
    const int by = blockIdx.y;   // M tiles
    const int tx = t & 15;       // 0..15 -> 8 cols each
    const int ty = t >> 4;       // 0..15 -> 8 rows each

    const float* Ab = A + (size_t)by * BM * lda;

    // A tile load mapping: 128 rows x 8 cols = 256 float4
    const int arow = t >> 1;
    const int acol = (t & 1) * 4;
    // B tile (nn) mapping: 8 rows x 128 cols = 256 float4
    const int brow = t >> 5;
    const int bcol = (t & 31) * 4;

    float acc[8][8];
#pragma unroll
    for (int i = 0; i < 8; i++)
#pragma unroll
        for (int j = 0; j < 8; j++) acc[i][j] = 0.0f;

    for (int k0 = 0; k0 < K; k0 += BK) {
        // A: store transposed for contiguous row access in MMA loop
        float4 av = *(const float4*)(Ab + (size_t)arow * lda + k0 + acol);
        As[acol + 0][arow] = av.x;
        As[acol + 1][arow] = av.y;
        As[acol + 2][arow] = av.z;
        As[acol + 3][arow] = av.w;

        if (BT) {
            // B is [N,K]: tile rows = n (128), cols = k (8); same pattern as A
            const float* Bb = B + (size_t)(bx * BN + arow) * ldb + k0 + acol;
            float4 bv = *(const float4*)Bb;
            Bs[acol + 0][arow] = bv.x;
            Bs[acol + 1][arow] = bv.y;
            Bs[acol + 2][arow] = bv.z;
            Bs[acol + 3][arow] = bv.w;
        } else {
            // B is [K,N]: tile rows = k (8), cols = n (128)
            const float* Bb = B + (size_t)(k0 + brow) * ldb + bx * BN + bcol;
            float4 bv = *(const float4*)Bb;
            *(float4*)&Bs[brow][bcol] = bv;
        }
        __syncthreads();

#pragma unroll
        for (int kk = 0; kk < BK; kk++) {
            float4 a0 = *(const float4*)&As[kk][ty * 8];
            float4 a1 = *(const float4*)&As[kk][ty * 8 + 4];
            float4 b0 = *(const float4*)&Bs[kk][tx * 8];
            float4 b1 = *(const float4*)&Bs[kk][tx * 8 + 4];
            float a[8] = {a0.x, a0.y, a0.z, a0.w, a1.x, a1.y, a1.z, a1.w};
            float b[8] = {b0.x, b0.y, b0.z, b0.w, b1.x, b1.y, b1.z, b1.w};
#pragma unroll
            for (int i = 0; i < 8; i++)
#pragma unroll
                for (int j = 0; j < 8; j++)
                    acc[i][j] = fmaf(a[i], b[j], acc[i][j]);
        }
        __syncthreads();
    }

    const int crow0 = by * BM + ty * 8;
    const int ccol0 = bx * BN + tx * 8;

    float bb[8];
    if (bias) {
#pragma unroll
        for (int j = 0; j < 8; j++) bb[j] = bias[ccol0 + j];
    } else {
#pragma unroll
        for (int j = 0; j < 8; j++) bb[j] = 0.0f;
    }

#pragma unroll
    for (int i = 0; i < 8; i++) {
        float* cp = C + (size_t)(crow0 + i) * ldc + ccol0;
        float4 r0 = make_float4(fmaf(alpha, acc[i][0], bb[0]),
                                fmaf(alpha, acc[i][1], bb[1]),
                                fmaf(alpha, acc[i][2], bb[2]),
                                fmaf(alpha, acc[i][3], bb[3]));
        float4 r1 = make_float4(fmaf(alpha, acc[i][4], bb[4]),
                                fmaf(alpha, acc[i][5], bb[5]),
                                fmaf(alpha, acc[i][6], bb[6]),
                                fmaf(alpha, acc[i][7], bb[7]));
        *(float4*)cp = r0;
        *(float4*)(cp + 4) = r1;
    }
}

// ---------------------------------------------------------------------------
// FF1: out = relu(LN(x @ W1 + b1)), x:[N,3], W1:[3,512]. One block per row.
// 128 threads, 4 columns each.
// ---------------------------------------------------------------------------
__global__ void __launch_bounds__(128) ff1_kernel(
    const float* __restrict__ x, const float* __restrict__ W1,
    const float* __restrict__ b1, const float* __restrict__ g1,
    const float* __restrict__ be1, float* __restrict__ out)
{
    const int row = blockIdx.x;
    const float x0 = x[row * 3 + 0];
    const float x1 = x[row * 3 + 1];
    const float x2 = x[row * 3 + 2];
    const int t = threadIdx.x;

    float v[4];
    float s = 0.0f, s2 = 0.0f;
#pragma unroll
    for (int i = 0; i < 4; i++) {
        int j = i * 128 + t;
        float val = fmaf(x0, W1[j], fmaf(x1, W1[DMODEL + j], fmaf(x2, W1[2 * DMODEL + j], b1[j])));
        v[i] = val;
        s += val;
        s2 = fmaf(val, val, s2);
    }
    s  = blockReduceSum(s);
    s2 = blockReduceSum(s2);
    const float mean = s * (1.0f / DMODEL);
    const float var  = s2 * (1.0f / DMODEL) - mean * mean;
    const float inv  = rsqrtf(var + 1e-5f);
#pragma unroll
    for (int i = 0; i < 4; i++) {
        int j = i * 128 + t;
        float y = fmaf((v[i] - mean) * inv, g1[j], be1[j]);
        out[(size_t)row * DMODEL + j] = fmaxf(y, 0.0f);
    }
}

// ---------------------------------------------------------------------------
// In-place LayerNorm + ReLU over rows of length D (D = 512 or 1024).
// One block per row, 256 threads, D/256 elems per thread (<=4).
// ---------------------------------------------------------------------------
__global__ void __launch_bounds__(256) ln_relu_kernel(
    float* __restrict__ X, int D,
    const float* __restrict__ g, const float* __restrict__ be)
{
    const int row = blockIdx.x;
    float* x = X + (size_t)row * D;
    const int t = threadIdx.x;
    const int per = D >> 8;  // D/256: 2 or 4

    float v[4];
    float s = 0.0f, s2 = 0.0f;
    for (int i = 0; i < per; i++) {
        float val = x[i * 256 + t];
        v[i] = val;
        s += val;
        s2 = fmaf(val, val, s2);
    }
    s  = blockReduceSum(s);
    s2 = blockReduceSum(s2);
    const float invD = 1.0f / (float)D;
    const float mean = s * invD;
    const float var  = s2 * invD - mean * mean;
    const float inv  = rsqrtf(var + 1e-5f);
    for (int i = 0; i < per; i++) {
        int j = i * 256 + t;
        float y = fmaf((v[i] - mean) * inv, g[j], be[j]);
        x[j] = fmaxf(y, 0.0f);
    }
}

// ---------------------------------------------------------------------------
// Row softmax over S[8192, 8192], one block per row, 256 threads.
// Whole row held in registers (32 floats/thread): 1 read + 1 write of S.
// ---------------------------------------------------------------------------
__global__ void __launch_bounds__(256) softmax_kernel(float* __restrict__ S)
{
    const size_t row = blockIdx.x;
    float4* s = (float4*)(S + row * (size_t)NROWS);
    const int t = threadIdx.x;

    float4 v[8];
    float m = -FLT_MAX;
#pragma unroll
    for (int i = 0; i < 8; i++) {
        v[i] = s[i * 256 + t];
        m = fmaxf(m, fmaxf(fmaxf(v[i].x, v[i].y), fmaxf(v[i].z, v[i].w)));
    }
    m = blockReduceMax(m);

    float sum = 0.0f;
#pragma unroll
    for (int i = 0; i < 8; i++) {
        v[i].x = __expf(v[i].x - m);
        v[i].y = __expf(v[i].y - m);
        v[i].z = __expf(v[i].z - m);
        v[i].w = __expf(v[i].w - m);
        sum += v[i].x + v[i].y + v[i].z + v[i].w;
    }
    sum = blockReduceSum(sum);
    const float inv = 1.0f / sum;
#pragma unroll
    for (int i = 0; i < 8; i++) {
        v[i].x *= inv; v[i].y *= inv; v[i].z *= inv; v[i].w *= inv;
        s[i * 256 + t] = v[i];
    }
}

// ---------------------------------------------------------------------------
// Host launch
// ---------------------------------------------------------------------------
static void launch_gemm_nn(int M, int N, int K,
                           const float* A, int lda, const float* B, int ldb,
                           float* C, int ldc, const float* bias, float alpha)
{
    dim3 grid(N / BN, M / BM);
    sgemm_kernel<false><<<grid, 256>>>(M, N, K, A, lda, B, ldb, C, ldc, bias, alpha);
}
static void launch_gemm_nt(int M, int N, int K,
                           const float* A, int lda, const float* B, int ldb,
                           float* C, int ldc, const float* bias, float alpha)
{
    dim3 grid(N / BN, M / BM);
    sgemm_kernel<true><<<grid, 256>>>(M, N, K, A, lda, B, ldb, C, ldc, bias, alpha);
}

extern "C" void kernel_launch(void* const* d_in, const int* in_sizes, int n_in,
                              void* d_out, int out_size)
{
    const float* x   = (const float*)d_in[0];
    const float* W1  = (const float*)d_in[1];
    const float* b1  = (const float*)d_in[2];
    const float* g1  = (const float*)d_in[3];
    const float* be1 = (const float*)d_in[4];
    const float* W2  = (const float*)d_in[5];
    const float* b2  = (const float*)d_in[6];
    const float* g2  = (const float*)d_in[7];
    const float* be2 = (const float*)d_in[8];
    const float* WQ  = (const float*)d_in[9];
    const float* WK  = (const float*)d_in[10];
    const float* WV  = (const float*)d_in[11];
    const float* WO  = (const float*)d_in[12];
    const float* Wf  = (const float*)d_in[13];
    const float* bf  = (const float*)d_in[14];
    const float* gf  = (const float*)d_in[15];
    const float* bef = (const float*)d_in[16];
    float* out = (float*)d_out;

    float *h, *tmp, *Q, *Km, *V, *S, *AV, *cat;
    cudaGetSymbolAddress((void**)&h,   g_h);
    cudaGetSymbolAddress((void**)&tmp, g_tmp);
    cudaGetSymbolAddress((void**)&Q,   g_Q);
    cudaGetSymbolAddress((void**)&Km,  g_Km);
    cudaGetSymbolAddress((void**)&V,   g_V);
    cudaGetSymbolAddress((void**)&S,   g_S);
    cudaGetSymbolAddress((void**)&AV,  g_AV);
    cudaGetSymbolAddress((void**)&cat, g_cat);

    const float inv_sqrt_md = 0.08838834764831845f;  // 1/sqrt(128)

    // FF1 (fused linear K=3 + LN + ReLU)
    ff1_kernel<<<NROWS, 128>>>(x, W1, b1, g1, be1, h);

    // FF2
    launch_gemm_nn(NROWS, DMODEL, DMODEL, h, DMODEL, W2, DMODEL, tmp, DMODEL, b2, 1.0f);
    ln_relu_kernel<<<NROWS, 256>>>(tmp, DMODEL, g2, be2);

    const float* cur = tmp;
    int ld_cur = DMODEL;

    for (int it = 0; it < 4; it++) {
        // Q, K, V projections
        launch_gemm_nn(NROWS, MDIM,   DMODEL, cur, ld_cur, WQ, MDIM,   Q,  MDIM,   nullptr, 1.0f);
        launch_gemm_nn(NROWS, MDIM,   DMODEL, cur, ld_cur, WK, MDIM,   Km, MDIM,   nullptr, 1.0f);
        launch_gemm_nn(NROWS, DMODEL, DMODEL, cur, ld_cur, WV, DMODEL, V,  DMODEL, nullptr, 1.0f);

        // S = Q @ K^T / sqrt(128)
        launch_gemm_nt(NROWS, NROWS, MDIM, Q, MDIM, Km, MDIM, S, NROWS, nullptr, inv_sqrt_md);

        // row softmax
        softmax_kernel<<<NROWS, 256>>>(S);

        // AV = S @ V
        launch_gemm_nn(NROWS, DMODEL, NROWS, S, NROWS, V, DMODEL, AV, DMODEL, nullptr, 1.0f);

        // a_it = AV @ WO -> cat[:, it*512 : (it+1)*512]
        float* a_out = cat + it * DMODEL;
        launch_gemm_nn(NROWS, DMODEL, DMODEL, AV, DMODEL, WO, DMODEL, a_out, 4 * DMODEL, nullptr, 1.0f);

        cur = a_out;
        ld_cur = 4 * DMODEL;
    }

    // Final FF: cat[8192,2048] @ Wf[2048,1024] + bf, then LN + ReLU
    launch_gemm_nn(NROWS, OUTF, 4 * DMODEL, cat, 4 * DMODEL, Wf, OUTF, out, OUTF, bf, 1.0f);
    ln_relu_kernel<<<NROWS, 256>>>(out, OUTF, gf, bef);
}

// round 3
// speedup vs baseline: 3.3268x; 3.3268x over previous
#include <cuda_runtime.h>
#include <math.h>
#include <float.h>
#include <stdint.h>

// ---------------------------------------------------------------------------
// PointEncoder: FF1 -> FF2 -> 4x attention -> concat -> FF_final
// N=8192, D=512, MD=128, OUT_F=1024.  TF32 tensor-core GEMMs, fp32 softmax/LN.
// ---------------------------------------------------------------------------

#define NROWS 8192
#define DMODEL 512
#define MDIM 128
#define OUTF 1024

// Static scratch
__device__ float g_h[NROWS * DMODEL];
__device__ float g_tmp[NROWS * DMODEL];
__device__ float g_Q[NROWS * MDIM];
__device__ float g_Km[NROWS * MDIM];
__device__ float g_V[NROWS * DMODEL];
__device__ float g_S[(size_t)NROWS * NROWS];       // 256 MB
__device__ float g_AV[NROWS * DMODEL];
__device__ float g_cat[NROWS * 4 * DMODEL];
// tf32-rounded weight copies
__device__ float g_W2r[DMODEL * DMODEL];
__device__ float g_WQr[DMODEL * MDIM];
__device__ float g_WKr[DMODEL * MDIM];
__device__ float g_WVr[DMODEL * DMODEL];
__device__ float g_WOr[DMODEL * DMODEL];
__device__ float g_Wfr[4 * DMODEL * OUTF];

__device__ __forceinline__ float to_tf32(float x) {
    uint32_t r;
    asm("cvt.rna.tf32.f32 %0, %1;" : "=r"(r) : "f"(x));
    return __uint_as_float(r);
}

// ---------------------------------------------------------------------------
// Reductions
// ---------------------------------------------------------------------------
__device__ __forceinline__ float warpReduceSum(float v) {
#pragma unroll
    for (int o = 16; o > 0; o >>= 1) v += __shfl_xor_sync(0xffffffff, v, o);
    return v;
}
__device__ __forceinline__ float warpReduceMax(float v) {
#pragma unroll
    for (int o = 16; o > 0; o >>= 1) v = fmaxf(v, __shfl_xor_sync(0xffffffff, v, o));
    return v;
}
__device__ float blockReduceSum(float v) {
    __shared__ float sh[32];
    __shared__ float res;
    int lane = threadIdx.x & 31, wid = threadIdx.x >> 5;
    v = warpReduceSum(v);
    if (lane == 0) sh[wid] = v;
    __syncthreads();
    int nw = (blockDim.x + 31) >> 5;
    float t = (threadIdx.x < nw) ? sh[threadIdx.x] : 0.0f;
    if (wid == 0) { t = warpReduceSum(t); if (lane == 0) res = t; }
    __syncthreads();
    return res;
}
__device__ float blockReduceMax(float v) {
    __shared__ float sh[32];
    __shared__ float res;
    int lane = threadIdx.x & 31, wid = threadIdx.x >> 5;
    v = warpReduceMax(v);
    if (lane == 0) sh[wid] = v;
    __syncthreads();
    int nw = (blockDim.x + 31) >> 5;
    float t = (threadIdx.x < nw) ? sh[threadIdx.x] : -FLT_MAX;
    if (wid == 0) { t = warpReduceMax(t); if (lane == 0) res = t; }
    __syncthreads();
    return res;
}

// ---------------------------------------------------------------------------
// cp.async helpers
// ---------------------------------------------------------------------------
__device__ __forceinline__ void cp16(float* dst, const float* src) {
    uint32_t d = (uint32_t)__cvta_generic_to_shared(dst);
    asm volatile("cp.async.cg.shared.global [%0], [%1], 16;\n" :: "r"(d), "l"(src));
}
__device__ __forceinline__ void cp_commit() { asm volatile("cp.async.commit_group;\n"); }
__device__ __forceinline__ void cp_wait1() { asm volatile("cp.async.wait_group 1;\n"); }
__device__ __forceinline__ void cp_wait0() { asm volatile("cp.async.wait_group 0;\n"); }

// ---------------------------------------------------------------------------
// TF32 GEMM: C[M,N] = alpha * A @ op(B) + bias  (optionally tf32-round output)
//   BT=false: B is [K,N] row-major;  BT=true: B is [N,K] row-major (C=A@B^T)
// 128x128x32 tile, 256 threads (8 warps, 2x4), warp tile 64x32, mma m16n8k8.
// M%128==0, N%128==0, K%32==0.
// ---------------------------------------------------------------------------
#define GBM 128
#define GBN 128
#define GBK 32

template <bool BT>
__global__ void __launch_bounds__(256, 2) gemm_tf32(
    int M, int N, int K,
    const float* __restrict__ A, int lda,
    const float* __restrict__ B, int ldb,
    float* __restrict__ C, int ldc,
    const float* __restrict__ bias, float alpha, int roundOut)
{
    constexpr int ASZ = 128 * 36;                    // floats per A stage
    constexpr int BSZ = BT ? 128 * 36 : 32 * 136;    // floats per B stage
    extern __shared__ float sm[];

    const int t    = threadIdx.x;
    const int wid  = t >> 5;
    const int lane = t & 31;
    const int g    = lane >> 2;   // 0..7
    const int t4   = lane & 3;    // 0..3
    const int wm   = wid & 1;     // 0..1 (64-row half)
    const int wn   = wid >> 1;    // 0..3 (32-col quarter)
    const int bx   = blockIdx.x;
    const int by   = blockIdx.y;

    const float* Ab = A + (size_t)by * GBM * lda;
    const float* Bb = BT ? (B + (size_t)bx * GBN * ldb) : (B + bx * GBN);

    // gmem->smem load mappings
    const int ar  = t >> 3;        // A/BT row (0..31, +32*i)
    const int ac  = (t & 7) * 4;   // A/BT col
    const int br  = t >> 5;        // B(NN) k-row (0..7, +8*i)
    const int bc4 = (t & 31) * 4;  // B(NN) n-col

    float acc[4][4][4];
#pragma unroll
    for (int mt = 0; mt < 4; mt++)
#pragma unroll
        for (int nt = 0; nt < 4; nt++)
#pragma unroll
            for (int r = 0; r < 4; r++) acc[mt][nt][r] = 0.0f;

    const int tiles = K / GBK;

    // ---- tile loader ----
    auto load_tile = [&](int stage, int k0) {
        float* as = sm + stage * ASZ;
        float* bs = sm + 2 * ASZ + stage * BSZ;
#pragma unroll
        for (int i = 0; i < 4; i++) {
            int row = ar + 32 * i;
            cp16(as + row * 36 + ac, Ab + (size_t)row * lda + k0 + ac);
        }
        if (BT) {
#pragma unroll
            for (int i = 0; i < 4; i++) {
                int row = ar + 32 * i;
                cp16(bs + row * 36 + ac, Bb + (size_t)row * ldb + k0 + ac);
            }
        } else {
#pragma unroll
            for (int i = 0; i < 4; i++) {
                int r = br + 8 * i;
                cp16(bs + r * 136 + bc4, Bb + (size_t)(k0 + r) * ldb + bc4);
            }
        }
        cp_commit();
    };

    load_tile(0, 0);

    for (int tt = 0; tt < tiles; tt++) {
        if (tt + 1 < tiles) {
            load_tile((tt + 1) & 1, (tt + 1) * GBK);
            cp_wait1();
        } else {
            cp_wait0();
        }
        __syncthreads();

        const int stage = tt & 1;
        const float* as = sm + stage * ASZ;
        const float* bs = sm + 2 * ASZ + stage * BSZ;
        const uint32_t* ap = (const uint32_t*)(as + (wm * 64 + g) * 36 + t4);
        const uint32_t* bp = BT ? (const uint32_t*)(bs + (wn * 32 + g) * 36 + t4)
                                : (const uint32_t*)(bs + t4 * 136 + wn * 32 + g);

#pragma unroll
        for (int k8 = 0; k8 < 4; k8++) {
            uint32_t a[4][4];
#pragma unroll
            for (int mt = 0; mt < 4; mt++) {
                a[mt][0] = ap[mt * 576 + k8 * 8];
                a[mt][1] = ap[mt * 576 + 288 + k8 * 8];
                a[mt][2] = ap[mt * 576 + k8 * 8 + 4];
                a[mt][3] = ap[mt * 576 + 288 + k8 * 8 + 4];
            }
            uint32_t b[4][2];
#pragma unroll
            for (int nt = 0; nt < 4; nt++) {
                if (BT) {
                    b[nt][0] = bp[nt * 288 + k8 * 8];
                    b[nt][1] = bp[nt * 288 + k8 * 8 + 4];
                } else {
                    b[nt][0] = bp[k8 * 8 * 136 + nt * 8];
                    b[nt][1] = bp[k8 * 8 * 136 + 544 + nt * 8];
                }
            }
#pragma unroll
            for (int mt = 0; mt < 4; mt++)
#pragma unroll
                for (int nt = 0; nt < 4; nt++) {
                    asm volatile(
                        "mma.sync.aligned.m16n8k8.row.col.f32.tf32.tf32.f32 "
                        "{%0,%1,%2,%3},{%4,%5,%6,%7},{%8,%9},{%0,%1,%2,%3};"
                        : "+f"(acc[mt][nt][0]), "+f"(acc[mt][nt][1]),
                          "+f"(acc[mt][nt][2]), "+f"(acc[mt][nt][3])
                        : "r"(a[mt][0]), "r"(a[mt][1]), "r"(a[mt][2]), "r"(a[mt][3]),
                          "r"(b[nt][0]), "r"(b[nt][1]));
                }
        }
        __syncthreads();
    }

    // ---- epilogue ----
#pragma unroll
    for (int mt = 0; mt < 4; mt++) {
        const int gr = by * GBM + wm * 64 + mt * 16 + g;
#pragma unroll
        for (int nt = 0; nt < 4; nt++) {
            const int gc = bx * GBN + wn * 32 + nt * 8 + 2 * t4;
            float b0 = bias ? bias[gc] : 0.0f;
            float b1 = bias ? bias[gc + 1] : 0.0f;
            float v0 = fmaf(alpha, acc[mt][nt][0], b0);
            float v1 = fmaf(alpha, acc[mt][nt][1], b1);
            float v2 = fmaf(alpha, acc[mt][nt][2], b0);
            float v3 = fmaf(alpha, acc[mt][nt][3], b1);
            if (roundOut) {
                v0 = to_tf32(v0); v1 = to_tf32(v1);
                v2 = to_tf32(v2); v3 = to_tf32(v3);
            }
            *(float2*)(C + (size_t)gr * ldc + gc)       = make_float2(v0, v1);
            *(float2*)(C + (size_t)(gr + 8) * ldc + gc) = make_float2(v2, v3);
        }
    }
}

// ---------------------------------------------------------------------------
// Weight round-to-tf32 copy
// ---------------------------------------------------------------------------
__global__ void cvt_tf32_kernel(const float4* __restrict__ in, float4* __restrict__ out, int n4)
{
    int i = blockIdx.x * blockDim.x + threadIdx.x;
    if (i < n4) {
        float4 v = in[i];
        v.x = to_tf32(v.x); v.y = to_tf32(v.y);
        v.z = to_tf32(v.z); v.w = to_tf32(v.w);
        out[i] = v;
    }
}

// ---------------------------------------------------------------------------
// FF1: out = tf32(relu(LN(x @ W1 + b1)))
// ---------------------------------------------------------------------------
__global__ void __launch_bounds__(128) ff1_kernel(
    const float* __restrict__ x, const float* __restrict__ W1,
    const float* __restrict__ b1, const float* __restrict__ g1,
    const float* __restrict__ be1, float* __restrict__ out)
{
    const int row = blockIdx.x;
    const float x0 = x[row * 3 + 0];
    const float x1 = x[row * 3 + 1];
    const float x2 = x[row * 3 + 2];
    const int t = threadIdx.x;

    float v[4];
    float s = 0.0f, s2 = 0.0f;
#pragma unroll
    for (int i = 0; i < 4; i++) {
        int j = i * 128 + t;
        float val = fmaf(x0, W1[j], fmaf(x1, W1[DMODEL + j], fmaf(x2, W1[2 * DMODEL + j], b1[j])));
        v[i] = val;
        s += val;
        s2 = fmaf(val, val, s2);
    }
    s  = blockReduceSum(s);
    s2 = blockReduceSum(s2);
    const float mean = s * (1.0f / DMODEL);
    const float var  = s2 * (1.0f / DMODEL) - mean * mean;
    const float inv  = rsqrtf(var + 1e-5f);
#pragma unroll
    for (int i = 0; i < 4; i++) {
        int j = i * 128 + t;
        float y = fmaf((v[i] - mean) * inv, g1[j], be1[j]);
        out[(size_t)row * DMODEL + j] = to_tf32(fmaxf(y, 0.0f));
    }
}

// ---------------------------------------------------------------------------
// In-place LayerNorm + ReLU (optionally tf32-round output)
// ---------------------------------------------------------------------------
__global__ void __launch_bounds__(256) ln_relu_kernel(
    float* __restrict__ X, int D,
    const float* __restrict__ g, const float* __restrict__ be, int roundOut)
{
    const int row = blockIdx.x;
    float* x = X + (size_t)row * D;
    const int t = threadIdx.x;
    const int per = D >> 8;

    float v[4];
    float s = 0.0f, s2 = 0.0f;
    for (int i = 0; i < per; i++) {
        float val = x[i * 256 + t];
        v[i] = val;
        s += val;
        s2 = fmaf(val, val, s2);
    }
    s  = blockReduceSum(s);
    s2 = blockReduceSum(s2);
    const float invD = 1.0f / (float)D;
    const float mean = s * invD;
    const float var  = s2 * invD - mean * mean;
    const float inv  = rsqrtf(var + 1e-5f);
    for (int i = 0; i < per; i++) {
        int j = i * 256 + t;
        float y = fmaxf(fmaf((v[i] - mean) * inv, g[j], be[j]), 0.0f);
        x[j] = roundOut ? to_tf32(y) : y;
    }
}

// ---------------------------------------------------------------------------
// Row softmax over S[8192, 8192]; writes tf32-rounded probs.
// ---------------------------------------------------------------------------
__global__ void __launch_bounds__(256) softmax_kernel(float* __restrict__ S)
{
    const size_t row = blockIdx.x;
    float4* s = (float4*)(S + row * (size_t)NROWS);
    const int t = threadIdx.x;

    float4 v[8];
    float m = -FLT_MAX;
#pragma unroll
    for (int i = 0; i < 8; i++) {
        v[i] = s[i * 256 + t];
        m = fmaxf(m, fmaxf(fmaxf(v[i].x, v[i].y), fmaxf(v[i].z, v[i].w)));
    }
    m = blockReduceMax(m);

    float sum = 0.0f;
#pragma unroll
    for (int i = 0; i < 8; i++) {
        v[i].x = __expf(v[i].x - m);
        v[i].y = __expf(v[i].y - m);
        v[i].z = __expf(v[i].z - m);
        v[i].w = __expf(v[i].w - m);
        sum += v[i].x + v[i].y + v[i].z + v[i].w;
    }
    sum = blockReduceSum(sum);
    const float inv = 1.0f / sum;
#pragma unroll
    for (int i = 0; i < 8; i++) {
        v[i].x = to_tf32(v[i].x * inv);
        v[i].y = to_tf32(v[i].y * inv);
        v[i].z = to_tf32(v[i].z * inv);
        v[i].w = to_tf32(v[i].w * inv);
        s[i * 256 + t] = v[i];
    }
}

// ---------------------------------------------------------------------------
// Host side
// ---------------------------------------------------------------------------
static const int SMEM_NN = (2 * 128 * 36 + 2 * 32 * 136) * 4;   // 71680
static const int SMEM_NT = (4 * 128 * 36) * 4;                  // 73728

static void launch_gemm_nn(int M, int N, int K,
                           const float* A, int lda, const float* B, int ldb,
                           float* C, int ldc, const float* bias, float alpha, int roundOut)
{
    dim3 grid(N / GBN, M / GBM);
    gemm_tf32<false><<<grid, 256, SMEM_NN>>>(M, N, K, A, lda, B, ldb, C, ldc, bias, alpha, roundOut);
}
static void launch_gemm_nt(int M, int N, int K,
                           const float* A, int lda, const float* B, int ldb,
                           float* C, int ldc, const float* bias, float alpha, int roundOut)
{
    dim3 grid(N / GBN, M / GBM);
    gemm_tf32<true><<<grid, 256, SMEM_NT>>>(M, N, K, A, lda, B, ldb, C, ldc, bias, alpha, roundOut);
}
static void launch_cvt(const float* in, float* out, int n)
{
    int n4 = n / 4;
    cvt_tf32_kernel<<<(n4 + 255) / 256, 256>>>((const float4*)in, (float4*)out, n4);
}

extern "C" void kernel_launch(void* const* d_in, const int* in_sizes, int n_in,
                              void* d_out, int out_size)
{
    const float* x   = (const float*)d_in[0];
    const float* W1  = (const float*)d_in[1];
    const float* b1  = (const float*)d_in[2];
    const float* g1  = (const float*)d_in[3];
    const float* be1 = (const float*)d_in[4];
    const float* W2  = (const float*)d_in[5];
    const float* b2  = (const float*)d_in[6];
    const float* g2  = (const float*)d_in[7];
    const float* be2 = (const float*)d_in[8];
    const float* WQ  = (const float*)d_in[9];
    const float* WK  = (const float*)d_in[10];
    const float* WV  = (const float*)d_in[11];
    const float* WO  = (const float*)d_in[12];
    const float* Wf  = (const float*)d_in[13];
    const float* bf  = (const float*)d_in[14];
    const float* gf  = (const float*)d_in[15];
    const float* bef = (const float*)d_in[16];
    float* out = (float*)d_out;

    cudaFuncSetAttribute(gemm_tf32<false>, cudaFuncAttributeMaxDynamicSharedMemorySize, SMEM_NN);
    cudaFuncSetAttribute(gemm_tf32<true>,  cudaFuncAttributeMaxDynamicSharedMemorySize, SMEM_NT);

    float *h, *tmp, *Q, *Km, *V, *S, *AV, *cat;
    float *W2r, *WQr, *WKr, *WVr, *WOr, *Wfr;
    cudaGetSymbolAddress((void**)&h,   g_h);
    cudaGetSymbolAddress((void**)&tmp, g_tmp);
    cudaGetSymbolAddress((void**)&Q,   g_Q);
    cudaGetSymbolAddress((void**)&Km,  g_Km);
    cudaGetSymbolAddress((void**)&V,   g_V);
    cudaGetSymbolAddress((void**)&S,   g_S);
    cudaGetSymbolAddress((void**)&AV,  g_AV);
    cudaGetSymbolAddress((void**)&cat, g_cat);
    cudaGetSymbolAddress((void**)&W2r, g_W2r);
    cudaGetSymbolAddress((void**)&WQr, g_WQr);
    cudaGetSymbolAddress((void**)&WKr, g_WKr);
    cudaGetSymbolAddress((void**)&WVr, g_WVr);
    cudaGetSymbolAddress((void**)&WOr, g_WOr);
    cudaGetSymbolAddress((void**)&Wfr, g_Wfr);

    // tf32-round all weights consumed by tensor-core GEMMs
    launch_cvt(W2, W2r, DMODEL * DMODEL);
    launch_cvt(WQ, WQr, DMODEL * MDIM);
    launch_cvt(WK, WKr, DMODEL * MDIM);
    launch_cvt(WV, WVr, DMODEL * DMODEL);
    launch_cvt(WO, WOr, DMODEL * DMODEL);
    launch_cvt(Wf, Wfr, 4 * DMODEL * OUTF);

    const float inv_sqrt_md = 0.08838834764831845f;  // 1/sqrt(128)

    // FF1 (K=3 fused) -> h (tf32-rounded)
    ff1_kernel<<<NROWS, 128>>>(x, W1, b1, g1, be1, h);

    // FF2
    launch_gemm_nn(NROWS, DMODEL, DMODEL, h, DMODEL, W2r, DMODEL, tmp, DMODEL, b2, 1.0f, 0);
    ln_relu_kernel<<<NROWS, 256>>>(tmp, DMODEL, g2, be2, 1);

    const float* cur = tmp;
    int ld_cur = DMODEL;

    for (int it = 0; it < 4; it++) {
        launch_gemm_nn(NROWS, MDIM,   DMODEL, cur, ld_cur, WQr, MDIM,   Q,  MDIM,   nullptr, 1.0f, 1);
        launch_gemm_nn(NROWS, MDIM,   DMODEL, cur, ld_cur, WKr, MDIM,   Km, MDIM,   nullptr, 1.0f, 1);
        launch_gemm_nn(NROWS, DMODEL, DMODEL, cur, ld_cur, WVr, DMODEL, V,  DMODEL, nullptr, 1.0f, 1);

        // S = Q @ K^T / sqrt(128)
        launch_gemm_nt(NROWS, NROWS, MDIM, Q, MDIM, Km, MDIM, S, NROWS, nullptr, inv_sqrt_md, 0);

        softmax_kernel<<<NROWS, 256>>>(S);

        // AV = S @ V
        launch_gemm_nn(NROWS, DMODEL, NROWS, S, NROWS, V, DMODEL, AV, DMODEL, nullptr, 1.0f, 1);

        // a_it = AV @ WO -> cat[:, it*512:(it+1)*512]
        float* a_out = cat + it * DMODEL;
        launch_gemm_nn(NROWS, DMODEL, DMODEL, AV, DMODEL, WOr, DMODEL, a_out, 4 * DMODEL, nullptr, 1.0f, 1);

        cur = a_out;
        ld_cur = 4 * DMODEL;
    }

    // Final FF
    launch_gemm_nn(NROWS, OUTF, 4 * DMODEL, cat, 4 * DMODEL, Wfr, OUTF, out, OUTF, bf, 1.0f, 0);
    ln_relu_kernel<<<NROWS, 256>>>(out, OUTF, gf, bef, 0);
}